// round 8
// baseline (speedup 1.0000x reference)
#include <cuda_runtime.h>
#include <cstdint>

#define SDIM 1024
#define BHN  64
#define THREADS 256
#define SLOT_BYTES 32768              /* A: 16KB (128x32 tf32) + B: 16KB (32x128) */
#define SMEM_BYTES (2 * SLOT_BYTES)   /* 64KB, double buffered */

// 256 MB scratch for attention probabilities.
__device__ __align__(16) float g_attn[(size_t)BHN * SDIM * SDIM];

__device__ __forceinline__ uint32_t f2tf(float x) {
    uint32_t r;
    asm("cvt.rna.tf32.f32 %0, %1;" : "=r"(r) : "f"(x));
    return r;
}

__device__ __forceinline__ uint32_t smem_u32(const void* p) {
    uint32_t a;
    asm("{ .reg .u64 t; cvta.to.shared.u64 t, %1; cvt.u32.u64 %0, t; }"
        : "=r"(a) : "l"(p));
    return a;
}

__device__ __forceinline__ void ldsm4(uint32_t a[4], uint32_t addr) {
    asm volatile("ldmatrix.sync.aligned.m8n8.x4.shared.b16 {%0,%1,%2,%3}, [%4];"
        : "=r"(a[0]), "=r"(a[1]), "=r"(a[2]), "=r"(a[3]) : "r"(addr));
}

__device__ __forceinline__ uint32_t lds32(uint32_t addr) {
    uint32_t v;
    asm volatile("ld.shared.b32 %0, [%1];" : "=r"(v) : "r"(addr));
    return v;
}

__device__ __forceinline__ void mma_tf32(float c[4], const uint32_t a[4],
                                         uint32_t b0, uint32_t b1) {
    asm volatile(
        "mma.sync.aligned.m16n8k8.row.col.f32.tf32.tf32.f32 "
        "{%0,%1,%2,%3}, {%4,%5,%6,%7}, {%8,%9}, {%0,%1,%2,%3};"
        : "+f"(c[0]), "+f"(c[1]), "+f"(c[2]), "+f"(c[3])
        : "r"(a[0]), "r"(a[1]), "r"(a[2]), "r"(a[3]), "r"(b0), "r"(b1));
}

// CTA tile 128x128, 8 warps (2x4), warp tile 64x32, mma m16n8k8 tf32.
// A smem: [m][32w] 128B rows, 16B-chunk swizzle ch^(m&7)  -> ldmatrix.x4 reads.
// B smem: [k][128w] 512B rows, word swizzle n^((k&7)<<3)  -> conflict-free LDS.32.
// Fragments are register double-buffered across k-steps (software pipeline).
// fuse_epi=1: out = (acc + AddM)*scale + Mask  (QK -> g_attn); 0: out = acc.
__global__ __launch_bounds__(THREADS, 2) void gemm_kernel(
    const float* __restrict__ Ag, const float* __restrict__ Bg,
    const float* __restrict__ AddM, const float* __restrict__ Mask,
    float* __restrict__ Out, int fuse_epi)
{
    extern __shared__ __align__(128) char smem[];
    const uint32_t sbase = smem_u32(smem);

    const int bm = blockIdx.x, bn = blockIdx.y, bh = blockIdx.z;
    const int tid  = threadIdx.x;
    const int warp = tid >> 5, lane = tid & 31;
    const int wm = warp >> 2, wn = warp & 3;   // 2 x 4 warp grid
    const int lr = lane >> 2, lc = lane & 3;

    const size_t mat = (size_t)bh * SDIM * SDIM;
    const float* Abase = Ag + mat + (size_t)(bm * 128) * SDIM;
    const float* Bbase = Bg + mat + bn * 128;

    float c[4][4][4];
    #pragma unroll
    for (int i = 0; i < 4; i++)
        #pragma unroll
        for (int j = 0; j < 4; j++)
            #pragma unroll
            for (int r = 0; r < 4; r++) c[i][j][r] = 0.f;

    // A fragment geometry (ldmatrix), verified rounds 3/5/6.
    const int moff = ((lane >> 3) & 1) * 8 + (lane & 7);
    const int csel = lane >> 4;
    uint32_t a_base[4];
    int      a_m7[4];
    #pragma unroll
    for (int ti = 0; ti < 4; ti++) {
        int m = wm * 64 + ti * 16 + moff;
        a_base[ti] = (uint32_t)m * 128u;
        a_m7[ti]   = m & 7;
    }
    // B fragment geometry: lane holds n = wn*32 + tj*8 + lr, k = kk + lc (+4).
    uint32_t nxb[4];
    #pragma unroll
    for (int tj = 0; tj < 4; tj++) {
        int n = wn * 32 + tj * 8 + lr;
        nxb[tj] = (uint32_t)((n ^ (lc << 3)) << 2);
    }

    // Per-thread fill coordinates (256 threads: 4 float4 each for A and B).
    const int fa_r  = tid >> 3;
    const int fa_ch = tid & 7;
    const int fb_k  = tid >> 5;
    const int fb_nq = (tid & 31) << 2;

    // ---- fill one slot (A tile 128x32, B tile 32x128) at k-offset kt ----
    auto fill = [&](int slot, int kt) {
        char* sA = smem + slot * SLOT_BYTES;
        char* sB = sA + 16384;
        #pragma unroll
        for (int i = 0; i < 4; ++i) {            // A: 1024 float4 / 256 thr
            int r  = fa_r + i * 32;
            float4 v = *reinterpret_cast<const float4*>(
                Abase + (size_t)r * SDIM + kt + fa_ch * 4);
            uint4 u;
            u.x = f2tf(v.x); u.y = f2tf(v.y); u.z = f2tf(v.z); u.w = f2tf(v.w);
            *reinterpret_cast<uint4*>(sA + r * 128 + ((fa_ch ^ (r & 7)) << 4)) = u;
        }
        #pragma unroll
        for (int i = 0; i < 4; ++i) {            // B: 1024 float4 / 256 thr
            int k  = fb_k + i * 8;
            float4 v = *reinterpret_cast<const float4*>(
                Bbase + (size_t)(kt + k) * SDIM + fb_nq);
            uint4 u;
            u.x = f2tf(v.x); u.y = f2tf(v.y); u.z = f2tf(v.z); u.w = f2tf(v.w);
            *reinterpret_cast<uint4*>(sB + k * 512 + ((fb_nq ^ ((k & 7) << 3)) << 2)) = u;
        }
    };

    // Fragment loaders for k-step kk4 (kk = kk4*8) from slot base addresses.
    auto load_a = [&](uint32_t sA, int kk4, uint32_t af[4][4]) {
        const int chunk = (kk4 << 1) + csel;
        #pragma unroll
        for (int ti = 0; ti < 4; ++ti)
            ldsm4(af[ti], sA + a_base[ti] + (uint32_t)((chunk ^ a_m7[ti]) << 4));
    };
    auto load_b = [&](uint32_t sB, int kk4, uint32_t b0[4], uint32_t b1[4]) {
        const uint32_t row0 = sB + (uint32_t)((kk4 << 3) + lc) * 512u;
        const uint32_t row1 = row0 + 2048u;
        #pragma unroll
        for (int tj = 0; tj < 4; ++tj) {
            b0[tj] = lds32(row0 + nxb[tj]);
            b1[tj] = lds32(row1 + (nxb[tj] ^ 128u));
        }
    };

    // ---- compute one slot with register double-buffered fragments ----
    auto compute = [&](int slot) {
        const uint32_t sA = sbase + slot * SLOT_BYTES;
        const uint32_t sB = sA + 16384;
        uint32_t af[2][4][4], b0[2][4], b1[2][4];
        load_a(sA, 0, af[0]);
        load_b(sB, 0, b0[0], b1[0]);
        #pragma unroll
        for (int kk4 = 0; kk4 < 4; ++kk4) {
            const int cur = kk4 & 1, nxt = cur ^ 1;
            if (kk4 < 3) {
                load_a(sA, kk4 + 1, af[nxt]);
                load_b(sB, kk4 + 1, b0[nxt], b1[nxt]);
            }
            #pragma unroll
            for (int ti = 0; ti < 4; ++ti)
                #pragma unroll
                for (int tj = 0; tj < 4; ++tj)
                    mma_tf32(c[ti][tj], af[cur][ti], b0[cur][tj], b1[cur][tj]);
        }
    };

    fill(0, 0);
    __syncthreads();
    #pragma unroll 1
    for (int it = 0; it < 32; ++it) {
        const int slot = it & 1;
        if (it < 31) fill(slot ^ 1, (it + 1) << 5);
        compute(slot);
        __syncthreads();
    }

    // ---- epilogue ----
    const float scale = 0.03125f;  // 1/sqrt(1024)
    #pragma unroll
    for (int ti = 0; ti < 4; ti++) {
        #pragma unroll
        for (int tj = 0; tj < 4; tj++) {
            int i0 = bm * 128 + wm * 64 + ti * 16 + lr;
            int j0 = bn * 128 + wn * 32 + tj * 8 + lc * 2;
            #pragma unroll
            for (int h = 0; h < 2; h++) {
                int i = i0 + h * 8;
                float v0 = c[ti][tj][h * 2 + 0];
                float v1 = c[ti][tj][h * 2 + 1];
                size_t off = mat + (size_t)i * SDIM + j0;
                if (fuse_epi) {
                    float2 bb = *reinterpret_cast<const float2*>(AddM + off);
                    float2 mm = *reinterpret_cast<const float2*>(
                        Mask + (size_t)i * SDIM + j0);
                    v0 = (v0 + bb.x) * scale + mm.x;
                    v1 = (v1 + bb.y) * scale + mm.y;
                }
                float2 o; o.x = v0; o.y = v1;
                *reinterpret_cast<float2*>(Out + off) = o;
            }
        }
    }
}

// One CTA (256 threads) per row of 1024; in-place softmax on g_attn.
__global__ __launch_bounds__(256) void softmax_kernel() {
    const size_t row = blockIdx.x;
    float* p = g_attn + row * SDIM;
    const int tid = threadIdx.x;
    const int warp = tid >> 5, lane = tid & 31;
    __shared__ float sred[8];

    float4 v = reinterpret_cast<float4*>(p)[tid];

    float m = fmaxf(fmaxf(v.x, v.y), fmaxf(v.z, v.w));
    #pragma unroll
    for (int o = 16; o; o >>= 1) m = fmaxf(m, __shfl_xor_sync(0xffffffffu, m, o));
    if (lane == 0) sred[warp] = m;
    __syncthreads();
    m = sred[0];
    #pragma unroll
    for (int i = 1; i < 8; i++) m = fmaxf(m, sred[i]);
    __syncthreads();

    v.x = expf(v.x - m);
    v.y = expf(v.y - m);
    v.z = expf(v.z - m);
    v.w = expf(v.w - m);
    float s = v.x + v.y + v.z + v.w;
    #pragma unroll
    for (int o = 16; o; o >>= 1) s += __shfl_xor_sync(0xffffffffu, s, o);
    if (lane == 0) sred[warp] = s;
    __syncthreads();
    s = sred[0];
    #pragma unroll
    for (int i = 1; i < 8; i++) s += sred[i];

    float inv = 1.0f / s;
    v.x *= inv; v.y *= inv; v.z *= inv; v.w *= inv;
    reinterpret_cast<float4*>(p)[tid] = v;
}

extern "C" void kernel_launch(void* const* d_in, const int* in_sizes, int n_in,
                              void* d_out, int out_size) {
    const float* A    = (const float*)d_in[0];
    const float* J    = (const float*)d_in[1];
    const float* B    = (const float*)d_in[2];
    const float* P    = (const float*)d_in[3];
    const float* mask = (const float*)d_in[4];
    float* out = (float*)d_out;

    float* attn = nullptr;
    cudaGetSymbolAddress((void**)&attn, g_attn);

    cudaFuncSetAttribute(gemm_kernel, cudaFuncAttributeMaxDynamicSharedMemorySize,
                         SMEM_BYTES);

    dim3 grid(SDIM / 128, SDIM / 128, BHN);  // 8 x 8 x 64
    gemm_kernel<<<grid, THREADS, SMEM_BYTES>>>(A, J, B, mask, attn, 1);
    softmax_kernel<<<BHN * SDIM, 256>>>();
    gemm_kernel<<<grid, THREADS, SMEM_BYTES>>>(attn, P, nullptr, nullptr, out, 0);
}

// round 9
// speedup vs baseline: 1.3189x; 1.3189x over previous
#include <cuda_runtime.h>
#include <cstdint>

#define SDIM 1024
#define BHN  64
#define THREADS 256
#define SLOT_BYTES 32768              /* A: 16KB (128x32 f32) + B: 16KB (32x128) */
#define STAGES 3
#define SMEM_BYTES (STAGES * SLOT_BYTES)   /* 96KB */

// 256 MB scratch for attention probabilities.
__device__ __align__(16) float g_attn[(size_t)BHN * SDIM * SDIM];

__device__ __forceinline__ uint32_t f2tf(float x) {
    uint32_t r;
    asm("cvt.rna.tf32.f32 %0, %1;" : "=r"(r) : "f"(x));
    return r;
}

__device__ __forceinline__ uint32_t smem_u32(const void* p) {
    uint32_t a;
    asm("{ .reg .u64 t; cvta.to.shared.u64 t, %1; cvt.u32.u64 %0, t; }"
        : "=r"(a) : "l"(p));
    return a;
}

__device__ __forceinline__ void cp16(uint32_t smem_dst, const void* gmem_src) {
    asm volatile("cp.async.cg.shared.global [%0], [%1], 16;"
                 :: "r"(smem_dst), "l"(gmem_src) : "memory");
}

__device__ __forceinline__ void cp_commit() {
    asm volatile("cp.async.commit_group;" ::: "memory");
}

__device__ __forceinline__ void cp_wait2() {
    asm volatile("cp.async.wait_group 2;" ::: "memory");
}

__device__ __forceinline__ void ldsm4(uint32_t a[4], uint32_t addr) {
    asm volatile("ldmatrix.sync.aligned.m8n8.x4.shared.b16 {%0,%1,%2,%3}, [%4];"
        : "=r"(a[0]), "=r"(a[1]), "=r"(a[2]), "=r"(a[3]) : "r"(addr));
}

__device__ __forceinline__ uint32_t lds32(uint32_t addr) {
    uint32_t v;
    asm volatile("ld.shared.b32 %0, [%1];" : "=r"(v) : "r"(addr));
    return v;
}

__device__ __forceinline__ void mma_tf32(float c[4], const uint32_t a[4],
                                         uint32_t b0, uint32_t b1) {
    asm volatile(
        "mma.sync.aligned.m16n8k8.row.col.f32.tf32.tf32.f32 "
        "{%0,%1,%2,%3}, {%4,%5,%6,%7}, {%8,%9}, {%0,%1,%2,%3};"
        : "+f"(c[0]), "+f"(c[1]), "+f"(c[2]), "+f"(c[3])
        : "r"(a[0]), "r"(a[1]), "r"(a[2]), "r"(a[3]), "r"(b0), "r"(b1));
}

// CTA tile 128x128, 8 warps (2x4), warp tile 64x32, mma m16n8k8 tf32.
// Tiles staged raw-fp32 via cp.async (3-stage ring); cvt->tf32 happens on the
// register fragments after ldmatrix/LDS.
// A smem: [m][32w] 128B rows, 16B-chunk swizzle ch^(m&7)  -> ldmatrix.x4 reads.
// B smem: [k][128w] 512B rows, word swizzle n^((k&7)<<3)  -> conflict-free LDS.32.
// fuse_epi=1: out = (acc + AddM)*scale + Mask  (QK -> g_attn); 0: out = acc.
__global__ __launch_bounds__(THREADS, 2) void gemm_kernel(
    const float* __restrict__ Ag, const float* __restrict__ Bg,
    const float* __restrict__ AddM, const float* __restrict__ Mask,
    float* __restrict__ Out, int fuse_epi)
{
    extern __shared__ __align__(128) char smem[];
    const uint32_t sbase = smem_u32(smem);

    const int bm = blockIdx.x, bn = blockIdx.y, bh = blockIdx.z;
    const int tid  = threadIdx.x;
    const int warp = tid >> 5, lane = tid & 31;
    const int wm = warp >> 2, wn = warp & 3;   // 2 x 4 warp grid
    const int lr = lane >> 2, lc = lane & 3;

    const size_t mat = (size_t)bh * SDIM * SDIM;
    const float* Abase = Ag + mat + (size_t)(bm * 128) * SDIM;
    const float* Bbase = Bg + mat + bn * 128;

    float c[4][4][4];
    #pragma unroll
    for (int i = 0; i < 4; i++)
        #pragma unroll
        for (int j = 0; j < 4; j++)
            #pragma unroll
            for (int r = 0; r < 4; r++) c[i][j][r] = 0.f;

    // A fragment geometry (ldmatrix), verified rounds 3/5/6/7.
    const int moff = ((lane >> 3) & 1) * 8 + (lane & 7);
    const int csel = lane >> 4;
    uint32_t a_base[4];
    int      a_m7[4];
    #pragma unroll
    for (int ti = 0; ti < 4; ti++) {
        int m = wm * 64 + ti * 16 + moff;
        a_base[ti] = (uint32_t)m * 128u;
        a_m7[ti]   = m & 7;
    }
    // B fragment geometry: lane holds n = wn*32 + tj*8 + lr, k = kk + lc (+4).
    uint32_t nxb[4];
    #pragma unroll
    for (int tj = 0; tj < 4; tj++) {
        int n = wn * 32 + tj * 8 + lr;
        nxb[tj] = (uint32_t)((n ^ (lc << 3)) << 2);
    }

    // Per-thread fill coordinates (256 threads: 4 x 16B each for A and B).
    const int fa_r  = tid >> 3;          // A rows fa_r + 32*i
    const int fa_ch = tid & 7;
    const int fb_k  = tid >> 5;          // B k-rows fb_k + 8*i
    const int fb_nq = (tid & 31) << 2;
    // Stage-relative destination offsets (kt-independent).
    uint32_t a_dst[4], b_dst[4];
    const float* a_src[4];
    const float* b_src[4];
    #pragma unroll
    for (int i = 0; i < 4; i++) {
        int r = fa_r + i * 32;
        a_dst[i] = (uint32_t)(r * 128 + ((fa_ch ^ (r & 7)) << 4));
        a_src[i] = Abase + (size_t)r * SDIM + fa_ch * 4;
        int k = fb_k + i * 8;
        b_dst[i] = (uint32_t)(16384 + k * 512 + ((fb_nq ^ ((k & 7) << 3)) << 2));
        b_src[i] = Bbase + (size_t)k * SDIM + fb_nq;
    }

    auto fill = [&](int stage, int kt) {
        const uint32_t s0 = sbase + stage * SLOT_BYTES;
        #pragma unroll
        for (int i = 0; i < 4; ++i) cp16(s0 + a_dst[i], a_src[i] + kt);
        #pragma unroll
        for (int i = 0; i < 4; ++i) cp16(s0 + b_dst[i], b_src[i] + (size_t)kt * SDIM);
    };

    // ---- compute one stage (raw fp32 in smem; cvt on fragments) ----
    auto compute = [&](int stage) {
        const uint32_t sA = sbase + stage * SLOT_BYTES;
        const uint32_t sB = sA + 16384;
        #pragma unroll
        for (int kk4 = 0; kk4 < 4; ++kk4) {
            uint32_t af[4][4];
            const int chunk = (kk4 << 1) + csel;
            #pragma unroll
            for (int ti = 0; ti < 4; ++ti)
                ldsm4(af[ti], sA + a_base[ti] + (uint32_t)((chunk ^ a_m7[ti]) << 4));

            uint32_t b0[4], b1[4];
            const uint32_t row0 = sB + (uint32_t)((kk4 << 3) + lc) * 512u;
            const uint32_t row1 = row0 + 2048u;
            #pragma unroll
            for (int tj = 0; tj < 4; ++tj) {
                b0[tj] = lds32(row0 + nxb[tj]);
                b1[tj] = lds32(row1 + (nxb[tj] ^ 128u));
            }
            // tf32 rounding on register fragments
            #pragma unroll
            for (int ti = 0; ti < 4; ++ti)
                #pragma unroll
                for (int j = 0; j < 4; ++j)
                    af[ti][j] = f2tf(__uint_as_float(af[ti][j]));
            #pragma unroll
            for (int tj = 0; tj < 4; ++tj) {
                b0[tj] = f2tf(__uint_as_float(b0[tj]));
                b1[tj] = f2tf(__uint_as_float(b1[tj]));
            }
            #pragma unroll
            for (int ti = 0; ti < 4; ++ti)
                #pragma unroll
                for (int tj = 0; tj < 4; ++tj)
                    mma_tf32(c[ti][tj], af[ti], b0[tj], b1[tj]);
        }
    };

    // Prologue: stages 0,1,2 <- tiles 0,1,2 (one commit group per tile).
    #pragma unroll
    for (int t = 0; t < STAGES; ++t) { fill(t, t << 5); cp_commit(); }

    #pragma unroll 1
    for (int it = 0; it < 32; ++it) {
        const int stage = it % STAGES;
        cp_wait2();          // tile `it` has arrived (this thread's copies)
        __syncthreads();     // all threads' copies visible
        compute(stage);
        __syncthreads();     // all warps done reading stage before refill
        if (it + STAGES < 32) fill(stage, (it + STAGES) << 5);
        cp_commit();         // unconditional: keeps group accounting uniform
    }

    // ---- epilogue ----
    const float scale = 0.03125f;  // 1/sqrt(1024)
    #pragma unroll
    for (int ti = 0; ti < 4; ti++) {
        #pragma unroll
        for (int tj = 0; tj < 4; tj++) {
            int i0 = bm * 128 + wm * 64 + ti * 16 + lr;
            int j0 = bn * 128 + wn * 32 + tj * 8 + lc * 2;
            #pragma unroll
            for (int h = 0; h < 2; h++) {
                int i = i0 + h * 8;
                float v0 = c[ti][tj][h * 2 + 0];
                float v1 = c[ti][tj][h * 2 + 1];
                size_t off = mat + (size_t)i * SDIM + j0;
                if (fuse_epi) {
                    float2 bb = *reinterpret_cast<const float2*>(AddM + off);
                    float2 mm = *reinterpret_cast<const float2*>(
                        Mask + (size_t)i * SDIM + j0);
                    v0 = (v0 + bb.x) * scale + mm.x;
                    v1 = (v1 + bb.y) * scale + mm.y;
                }
                float2 o; o.x = v0; o.y = v1;
                *reinterpret_cast<float2*>(Out + off) = o;
            }
        }
    }
}

// One CTA (256 threads) per row of 1024; in-place softmax on g_attn.
__global__ __launch_bounds__(256) void softmax_kernel() {
    const size_t row = blockIdx.x;
    float* p = g_attn + row * SDIM;
    const int tid = threadIdx.x;
    const int warp = tid >> 5, lane = tid & 31;
    __shared__ float sred[8];

    float4 v = reinterpret_cast<float4*>(p)[tid];

    float m = fmaxf(fmaxf(v.x, v.y), fmaxf(v.z, v.w));
    #pragma unroll
    for (int o = 16; o; o >>= 1) m = fmaxf(m, __shfl_xor_sync(0xffffffffu, m, o));
    if (lane == 0) sred[warp] = m;
    __syncthreads();
    m = sred[0];
    #pragma unroll
    for (int i = 1; i < 8; i++) m = fmaxf(m, sred[i]);
    __syncthreads();

    v.x = expf(v.x - m);
    v.y = expf(v.y - m);
    v.z = expf(v.z - m);
    v.w = expf(v.w - m);
    float s = v.x + v.y + v.z + v.w;
    #pragma unroll
    for (int o = 16; o; o >>= 1) s += __shfl_xor_sync(0xffffffffu, s, o);
    if (lane == 0) sred[warp] = s;
    __syncthreads();
    s = sred[0];
    #pragma unroll
    for (int i = 1; i < 8; i++) s += sred[i];

    float inv = 1.0f / s;
    v.x *= inv; v.y *= inv; v.z *= inv; v.w *= inv;
    reinterpret_cast<float4*>(p)[tid] = v;
}

extern "C" void kernel_launch(void* const* d_in, const int* in_sizes, int n_in,
                              void* d_out, int out_size) {
    const float* A    = (const float*)d_in[0];
    const float* J    = (const float*)d_in[1];
    const float* B    = (const float*)d_in[2];
    const float* P    = (const float*)d_in[3];
    const float* mask = (const float*)d_in[4];
    float* out = (float*)d_out;

    float* attn = nullptr;
    cudaGetSymbolAddress((void**)&attn, g_attn);

    cudaFuncSetAttribute(gemm_kernel, cudaFuncAttributeMaxDynamicSharedMemorySize,
                         SMEM_BYTES);

    dim3 grid(SDIM / 128, SDIM / 128, BHN);  // 8 x 8 x 64
    gemm_kernel<<<grid, THREADS, SMEM_BYTES>>>(A, J, B, mask, attn, 1);
    softmax_kernel<<<BHN * SDIM, 256>>>();
    gemm_kernel<<<grid, THREADS, SMEM_BYTES>>>(attn, P, nullptr, nullptr, out, 0);
}